// round 7
// baseline (speedup 1.0000x reference)
#include <cuda_runtime.h>
#include <cstdint>

// Merton jump diffusion — barrier-free per-warp scan with a 4-stage cp.async
// input pipeline (loads continuously in flight) and SMEM micro-transpose output.
//   paths[p,0]   = S0
//   paths[p,t+1] = S0 * exp( sum_{u<=t} drift[u] + CDIFF*zd[u,p] + sqrtJ(nj[u,p])*zj[u,p] )

#define N_STEPS   2048
#define N_PATHS   32768
#define TPB       64
#define WARPS     (TPB / 32)
#define SSTEPS    8                      // steps per pipeline stage
#define NSLOTS    4                      // pipeline depth
#define NSTAGES   (N_STEPS / SSTEPS)     // 256
#define TILE      32
#define N_CHUNKS  (N_STEPS / TILE)       // 64
#define OUT_COLS  (N_STEPS + 1)
#define JT_SIZE   32
#define ROWPAD    36

__device__ __forceinline__ void cp_async4(unsigned s, const void* g) {
    asm volatile("cp.async.ca.shared.global [%0], [%1], 4;" :: "r"(s), "l"(g));
}
__device__ __forceinline__ void cp_commit() {
    asm volatile("cp.async.commit_group;" ::: "memory");
}
__device__ __forceinline__ void cp_wait3() {
    asm volatile("cp.async.wait_group 3;" ::: "memory");
}

__global__ __launch_bounds__(TPB) void merton_kernel(
    const float* __restrict__ S0p,
    const float* __restrict__ zd,
    const float* __restrict__ zj,
    const int*   __restrict__ njp,
    float*       __restrict__ out)
{
    __shared__ float drift_s[N_STEPS];                    // 8 KB
    __shared__ float jtab[JT_SIZE];
    __shared__ float zbuf[NSLOTS][SSTEPS][TPB * 2];       // 16 KB: (zd, zj) interleaved
    __shared__ int   nbuf[NSLOTS][SSTEPS][TPB];           // 8 KB
    __shared__ float tbuf[WARPS][TILE][ROWPAD];           // 9.2 KB transpose tiles

    const int tid   = threadIdx.x;
    const int lane  = tid & 31;
    const int warp  = tid >> 5;
    const int wbase = blockIdx.x * TPB + warp * 32;
    const int p     = wbase + lane;

    const float DT    = 1.0f / 2048.0f;
    const float KAPPA = 0.04602785990f;              // exp(0.045) - 1 (fp32)
    const float CDIFF = 0.2f * 0.02209708691f;       // SIGMA * fl(sqrt(DT)), ref fp32 order

    for (int i = tid; i < N_STEPS; i += TPB) {
        float t   = (float)i * DT;
        float lam = 0.1f + 0.9f * expf(-0.01f * t);
        drift_s[i] = (0.0f - lam * KAPPA) * DT;
    }
    if (tid < JT_SIZE) jtab[tid] = sqrtf((float)tid) * 0.3f;

    const float s0 = S0p[0];
    __syncthreads();                                 // one-time: tables ready

    out[p * OUT_COLS] = s0;                          // column 0

    const unsigned zsm = (unsigned)__cvta_generic_to_shared(&zbuf[0][0][0]);
    const unsigned nsm = (unsigned)__cvta_generic_to_shared(&nbuf[0][0][0]);

    // Issue one stage's loads (24 cp.async of 4B each, fully coalesced per warp)
    auto issue_stage = [&](int st, int slot) {
        const int base = st * SSTEPS * N_PATHS + p;
        #pragma unroll
        for (int s = 0; s < SSTEPS; ++s) {
            const int idx = base + s * N_PATHS;
            const unsigned zs = zsm + (unsigned)(((slot * SSTEPS + s) * TPB + tid) * 2) * 4u;
            cp_async4(zs,      zd  + idx);
            cp_async4(zs + 4u, zj  + idx);
            cp_async4(nsm + (unsigned)((slot * SSTEPS + s) * TPB + tid) * 4u, njp + idx);
        }
        cp_commit();
    };

    // Prologue: stages 0..2 in flight
    issue_stage(0, 0);
    issue_stage(1, 1);
    issue_stage(2, 2);

    float acc = 0.0f;
    float v[TILE];

    for (int c = 0; c < N_CHUNKS; ++c) {
        #pragma unroll
        for (int sub = 0; sub < 4; ++sub) {          // slot of stage st = sub (c*4 ≡ 0 mod 4)
            const int st = c * 4 + sub;

            // Keep 3 stages ahead in flight; empty commit keeps group count uniform
            if (st + 3 < NSTAGES) issue_stage(st + 3, (sub + 3) & 3);
            else                  cp_commit();
            cp_wait3();                               // stage st's data landed

            const int tb = st * SSTEPS;
            #pragma unroll
            for (int s = 0; s < SSTEPS; ++s) {
                float2 zz = *reinterpret_cast<float2*>(&zbuf[sub][s][tid * 2]);
                int n = nbuf[sub][s][tid];
                n = (n < JT_SIZE) ? n : (JT_SIZE - 1);
                acc += drift_s[tb + s] + CDIFF * zz.x + jtab[n] * zz.y;
                v[sub * SSTEPS + s] = s0 * __expf(acc);
            }
        }

        // Transpose 32x32 tile through per-warp SMEM (syncwarp only)
        #pragma unroll
        for (int s = 0; s < TILE; s += 4) {
            *reinterpret_cast<float4*>(&tbuf[warp][lane][s]) =
                make_float4(v[s], v[s + 1], v[s + 2], v[s + 3]);
        }
        __syncwarp();

        const int tbc = c * TILE;
        #pragma unroll
        for (int j = 0; j < TILE; ++j) {
            __stcs(&out[(wbase + j) * OUT_COLS + 1 + tbc + lane], tbuf[warp][j][lane]);
        }
        __syncwarp();                                 // WAR before next chunk's STS
    }
}

extern "C" void kernel_launch(void* const* d_in, const int* in_sizes, int n_in,
                              void* d_out, int out_size)
{
    const float* S0 = (const float*)d_in[0];
    const float* zd = (const float*)d_in[1];
    const float* zj = (const float*)d_in[2];
    const int*   nj = (const int*)  d_in[3];
    float*       out = (float*)d_out;

    merton_kernel<<<N_PATHS / TPB, TPB>>>(S0, zd, zj, nj, out);
}

// round 10
// speedup vs baseline: 1.2476x; 1.2476x over previous
#include <cuda_runtime.h>

// Merton jump diffusion — per-warp scan with QUARTER-INTERLEAVED rolling LDG
// prefetch (loads continuously in flight; load->use distance ~1 full chunk)
// and per-warp SMEM micro-transpose for coalesced output.
//   paths[p,0]   = S0
//   paths[p,t+1] = S0 * exp( sum_{u<=t} drift[u] + CDIFF*zd[u,p] + sqrtJ(nj[u,p])*zj[u,p] )

#define N_STEPS   2048
#define N_PATHS   32768
#define TPB       64
#define WARPS     (TPB / 32)
#define TILE      32
#define QUART     8
#define N_CHUNKS  (N_STEPS / TILE)       // 64
#define OUT_COLS  (N_STEPS + 1)
#define JT_SIZE   32
#define ROWPAD    36

__global__ __launch_bounds__(TPB) void merton_kernel(
    const float* __restrict__ S0p,
    const float* __restrict__ zd,
    const float* __restrict__ zj,
    const int*   __restrict__ njp,
    float*       __restrict__ out)
{
    __shared__ float drift_s[N_STEPS];               // 8 KB, broadcast reads
    __shared__ float jtab[JT_SIZE];
    __shared__ float tbuf[WARPS][TILE][ROWPAD];      // 9.2 KB transpose tiles

    const int tid   = threadIdx.x;
    const int lane  = tid & 31;
    const int warp  = tid >> 5;
    const int wbase = blockIdx.x * TPB + warp * 32;  // warp's first path
    const int p     = wbase + lane;

    const float DT    = 1.0f / 2048.0f;
    const float KAPPA = 0.04602785990f;              // exp(0.045) - 1 (fp32)
    const float CDIFF = 0.2f * 0.02209708691f;       // SIGMA * fl(sqrt(DT)), ref fp32 order

    for (int i = tid; i < N_STEPS; i += TPB) {
        float t   = (float)i * DT;
        float lam = 0.1f + 0.9f * expf(-0.01f * t);
        drift_s[i] = (0.0f - lam * KAPPA) * DT;
    }
    if (tid < JT_SIZE) jtab[tid] = sqrtf((float)tid) * 0.3f;

    const float s0 = S0p[0];
    __syncthreads();                                 // one-time: tables ready

    out[p * OUT_COLS] = s0;                          // column 0

    // Rolling register buffer for one chunk (32 steps x 3 arrays = 96 LDGs)
    float r1[TILE], r2[TILE];
    int   r3[TILE];

    // Prologue: chunk 0 fully loaded
    #pragma unroll
    for (int s = 0; s < TILE; ++s) {
        const int idx = s * N_PATHS + p;
        r1[s] = __ldcs(zd + idx);
        r2[s] = __ldcs(zj + idx);
        r3[s] = __ldcs(njp + idx);
    }

    float acc = 0.0f;
    float v[TILE];

    for (int c = 0; c < N_CHUNKS; ++c) {
        const int tb = c * TILE;

        #pragma unroll
        for (int q = 0; q < 4; ++q) {
            // Compute this quarter (consumes regs q*8 .. q*8+7)
            #pragma unroll
            for (int k = 0; k < QUART; ++k) {
                const int s = q * QUART + k;
                int n = r3[s];  n = (n < JT_SIZE) ? n : (JT_SIZE - 1);
                acc += drift_s[tb + s] + CDIFF * r1[s] + jtab[n] * r2[s];
                v[s] = s0 * __expf(acc);
            }
            // Immediately refill the just-freed quarter with next chunk's loads.
            // These sit in flight for ~1 full chunk before consumption.
            if (c + 1 < N_CHUNKS) {
                #pragma unroll
                for (int k = 0; k < QUART; ++k) {
                    const int s   = q * QUART + k;
                    const int idx = (tb + TILE + s) * N_PATHS + p;
                    r1[s] = __ldcs(zd + idx);
                    r2[s] = __ldcs(zj + idx);
                    r3[s] = __ldcs(njp + idx);
                }
            }
        }

        // Transpose 32x32 tile through per-warp SMEM (syncwarp only, conflict-free)
        #pragma unroll
        for (int s = 0; s < TILE; s += 4) {
            *reinterpret_cast<float4*>(&tbuf[warp][lane][s]) =
                make_float4(v[s], v[s + 1], v[s + 2], v[s + 3]);
        }
        __syncwarp();

        #pragma unroll
        for (int j = 0; j < TILE; ++j) {
            __stcs(&out[(wbase + j) * OUT_COLS + 1 + tb + lane], tbuf[warp][j][lane]);
        }
        __syncwarp();                                // WAR before next chunk's STS
    }
}

extern "C" void kernel_launch(void* const* d_in, const int* in_sizes, int n_in,
                              void* d_out, int out_size)
{
    const float* S0 = (const float*)d_in[0];
    const float* zd = (const float*)d_in[1];
    const float* zj = (const float*)d_in[2];
    const int*   nj = (const int*)  d_in[3];
    float*       out = (float*)d_out;

    merton_kernel<<<N_PATHS / TPB, TPB>>>(S0, zd, zj, nj, out);
}

// round 15
// speedup vs baseline: 1.4262x; 1.1431x over previous
#include <cuda_runtime.h>

// Merton jump diffusion — per-warp scan, rolling quarter-interleaved prefetch for
// zd/n, and PREDICATED z_jump loads (only where n_jumps>0; ~0.05% of elements),
// cutting total DRAM traffic by ~25%. SMEM micro-transpose, STG.32 drain
// (output row stride 2049 is odd -> vector stores are structurally misaligned).
//   paths[p,0]   = S0
//   paths[p,t+1] = S0 * exp( sum_{u<=t} drift[u] + CDIFF*zd[u,p] + sqrt(nj[u,p])*0.3*zj[u,p] )

#define N_STEPS   2048
#define N_PATHS   32768
#define TPB       64
#define WARPS     (TPB / 32)
#define TILE      32
#define QUART     8
#define N_CHUNKS  (N_STEPS / TILE)       // 64
#define OUT_COLS  (N_STEPS + 1)
#define JT_SIZE   32
#define ROWPAD    36

__global__ __launch_bounds__(TPB) void merton_kernel(
    const float* __restrict__ S0p,
    const float* __restrict__ zd,
    const float* __restrict__ zj,
    const int*   __restrict__ njp,
    float*       __restrict__ out)
{
    __shared__ float drift_s[N_STEPS];               // 8 KB, broadcast reads
    __shared__ float jtab[JT_SIZE];
    __shared__ float tbuf[WARPS][TILE][ROWPAD];      // 9.2 KB transpose tiles

    const int tid   = threadIdx.x;
    const int lane  = tid & 31;
    const int warp  = tid >> 5;
    const int wbase = blockIdx.x * TPB + warp * 32;  // warp's first path
    const int p     = wbase + lane;

    const float DT    = 1.0f / 2048.0f;
    const float KAPPA = 0.04602785990f;              // exp(0.045) - 1 (fp32)
    const float CDIFF = 0.2f * 0.02209708691f;       // SIGMA * fl(sqrt(DT)), ref fp32 order

    for (int i = tid; i < N_STEPS; i += TPB) {
        float t   = (float)i * DT;
        float lam = 0.1f + 0.9f * expf(-0.01f * t);
        drift_s[i] = (0.0f - lam * KAPPA) * DT;
    }
    if (tid < JT_SIZE) jtab[tid] = sqrtf((float)tid) * 0.3f;

    const float s0 = S0p[0];
    __syncthreads();                                 // one-time: tables ready

    out[p * OUT_COLS] = s0;                          // column 0

    // Rolling register buffers: zd + n unconditional, zj conditional (n>0 only)
    float r1[TILE], r2[TILE];
    int   r3[TILE];

    #pragma unroll
    for (int s = 0; s < TILE; ++s) r2[s] = 0.0f;

    // Prologue: chunk 0 zd + n, then conditional zj for quarter 0
    #pragma unroll
    for (int s = 0; s < TILE; ++s) {
        const int idx = s * N_PATHS + p;
        r1[s] = __ldcs(zd + idx);
        r3[s] = __ldcs(njp + idx);
    }
    #pragma unroll
    for (int s = 0; s < QUART; ++s) {
        if (r3[s] > 0) r2[s] = __ldcs(zj + s * N_PATHS + p);
    }

    float acc = 0.0f;
    float v[TILE];

    for (int c = 0; c < N_CHUNKS; ++c) {
        const int tb = c * TILE;

        #pragma unroll
        for (int q = 0; q < 4; ++q) {
            // --- Compute quarter q (r2 valid wherever n>0; gated otherwise) ---
            #pragma unroll
            for (int k = 0; k < QUART; ++k) {
                const int s = q * QUART + k;
                int n = r3[s];
                int nc = (n < JT_SIZE) ? n : (JT_SIZE - 1);
                float jterm = (n > 0) ? jtab[nc] * r2[s] : 0.0f;
                acc += drift_s[tb + s] + CDIFF * r1[s] + jterm;
                v[s] = s0 * __expf(acc);
            }

            // --- Refill just-freed quarter with next chunk's zd + n ---
            if (c + 1 < N_CHUNKS) {
                #pragma unroll
                for (int k = 0; k < QUART; ++k) {
                    const int s   = q * QUART + k;
                    const int idx = (tb + TILE + s) * N_PATHS + p;
                    r1[s] = __ldcs(zd + idx);
                    r3[s] = __ldcs(njp + idx);
                }
            }

            // --- Conditional zj prefetch for the NEXT quarter ---
            // q<3: quarter q+1 of this chunk (r3 slots still hold chunk c counts).
            // q==3: quarter 0 of chunk c+1 (r3 slots 0..7 refilled at q=0, arrived).
            if (q < 3 || c + 1 < N_CHUNKS) {
                const int nq    = (q + 1) & 3;
                const int cbase = (q < 3) ? tb : (tb + TILE);
                #pragma unroll
                for (int k = 0; k < QUART; ++k) {
                    const int s2 = nq * QUART + k;
                    if (r3[s2] > 0) r2[s2] = __ldcs(zj + (cbase + s2) * N_PATHS + p);
                }
            }
        }

        // Transpose 32x32 tile through per-warp SMEM (syncwarp only, conflict-free)
        #pragma unroll
        for (int s = 0; s < TILE; s += 4) {
            *reinterpret_cast<float4*>(&tbuf[warp][lane][s]) =
                make_float4(v[s], v[s + 1], v[s + 2], v[s + 3]);
        }
        __syncwarp();

        #pragma unroll
        for (int j = 0; j < TILE; ++j) {
            __stcs(&out[(wbase + j) * OUT_COLS + 1 + tb + lane], tbuf[warp][j][lane]);
        }
        __syncwarp();                                // WAR before next chunk's STS
    }
}

extern "C" void kernel_launch(void* const* d_in, const int* in_sizes, int n_in,
                              void* d_out, int out_size)
{
    const float* S0 = (const float*)d_in[0];
    const float* zd = (const float*)d_in[1];
    const float* zj = (const float*)d_in[2];
    const int*   nj = (const int*)  d_in[3];
    float*       out = (float*)d_out;

    merton_kernel<<<N_PATHS / TPB, TPB>>>(S0, zd, zj, nj, out);
}